// round 12
// baseline (speedup 1.0000x reference)
#include <cuda_runtime.h>
#include <math.h>

static constexpr int H  = 512;
static constexpr int G4 = 2048;
static constexpr int B  = 128;
static constexpr int T  = 256;
static constexpr int V  = 128;
static constexpr int LW = 32;
static constexpr int NL = 2;
static constexpr int BH = B * H;
static constexpr int E2 = 2 * H;
static constexpr int KC = 32;       // k-chunk
static constexpr int AS = 20;       // a_sm row stride (pad: conflict-free, 16B-aligned)

static constexpr long OUT_HF  = (long)B * LW * V;
static constexpr long OUT_CF  = OUT_HF + (long)NL * BH;
static constexpr long OUT_ATT = OUT_CF + (long)NL * BH;

// ---- scratch (device globals; no runtime allocation) ----
__device__ float g_l0[(size_t)T * B * E2];   // layer0 out [t][b][2H]
__device__ float g_enc[(size_t)B * T * E2];  // encoder out [b][t][2H]
__device__ float g_eh[2 * 2 * BH];           // enc h [phase][dir][B][H]
__device__ float g_ec[2 * BH];               // enc c [dir][B][H]
__device__ float g_dh[2 * 2 * BH];           // dec h [phase][layer][B][H]
__device__ float g_dc[2 * BH];               // dec c [layer][B][H]
__device__ float g_din[BH];
__device__ float g_q[B * E2];
__device__ float g_cx[B * E2];
__device__ float g_cb[BH];
__device__ int   g_tok[B];

__device__ __forceinline__ float sigf(float x) { return 1.0f / (1.0f + expf(-x)); }

// ========== LSTM GEMM: 16 rows x 128 gate-cols, 128 threads, 4x4/thread ==========
// a_sm: 2*KC*AS floats ([k][row], padded), w_sm: 2*KC*128 floats ([k][col]).
// Double-buffered smem + global register prefetch + register software pipeline
// of the smem reads (k+1 loaded before k's FFMAs). One barrier per 32-k chunk.
__device__ __forceinline__ void lstm_tile_acc(float acc[4][4],
    const float* __restrict__ A, int lda, int K,
    const float* __restrict__ W, int ldw, int wcol,
    float* a_sm, float* w_sm, int tid, int rg4, int cg4)
{
    const int ar  = tid & 15;          // row 0..15
    const int akk = (tid >> 4) * 4;    // k-group 0,4,...,28
    const int wk  = tid >> 5;          // 0..3
    float4 av, wv0, wv1, wv2, wv3, wv4, wv5, wv6, wv7;
    av  = *(const float4*)(A + (size_t)ar * lda + akk);
    wv0 = *(const float4*)(W + (size_t)(wk +  0) * ldw + wcol);
    wv1 = *(const float4*)(W + (size_t)(wk +  4) * ldw + wcol);
    wv2 = *(const float4*)(W + (size_t)(wk +  8) * ldw + wcol);
    wv3 = *(const float4*)(W + (size_t)(wk + 12) * ldw + wcol);
    wv4 = *(const float4*)(W + (size_t)(wk + 16) * ldw + wcol);
    wv5 = *(const float4*)(W + (size_t)(wk + 20) * ldw + wcol);
    wv6 = *(const float4*)(W + (size_t)(wk + 24) * ldw + wcol);
    wv7 = *(const float4*)(W + (size_t)(wk + 28) * ldw + wcol);
    __syncthreads();
    a_sm[(akk + 0) * AS + ar] = av.x;
    a_sm[(akk + 1) * AS + ar] = av.y;
    a_sm[(akk + 2) * AS + ar] = av.z;
    a_sm[(akk + 3) * AS + ar] = av.w;
    *(float4*)(w_sm + (wk +  0) * 128 + cg4) = wv0;
    *(float4*)(w_sm + (wk +  4) * 128 + cg4) = wv1;
    *(float4*)(w_sm + (wk +  8) * 128 + cg4) = wv2;
    *(float4*)(w_sm + (wk + 12) * 128 + cg4) = wv3;
    *(float4*)(w_sm + (wk + 16) * 128 + cg4) = wv4;
    *(float4*)(w_sm + (wk + 20) * 128 + cg4) = wv5;
    *(float4*)(w_sm + (wk + 24) * 128 + cg4) = wv6;
    *(float4*)(w_sm + (wk + 28) * 128 + cg4) = wv7;
    __syncthreads();
    int buf = 0;
    for (int kt = 0; kt < K; kt += KC) {
        const bool more = (kt + KC < K);
        if (more) {
            const float* An = A + (size_t)ar * lda + kt + KC;
            const float* Wn = W + (size_t)(kt + KC) * ldw + wcol;
            av  = *(const float4*)(An + akk);
            wv0 = *(const float4*)(Wn + (size_t)(wk +  0) * ldw);
            wv1 = *(const float4*)(Wn + (size_t)(wk +  4) * ldw);
            wv2 = *(const float4*)(Wn + (size_t)(wk +  8) * ldw);
            wv3 = *(const float4*)(Wn + (size_t)(wk + 12) * ldw);
            wv4 = *(const float4*)(Wn + (size_t)(wk + 16) * ldw);
            wv5 = *(const float4*)(Wn + (size_t)(wk + 20) * ldw);
            wv6 = *(const float4*)(Wn + (size_t)(wk + 24) * ldw);
            wv7 = *(const float4*)(Wn + (size_t)(wk + 28) * ldw);
        }
        const float* as = a_sm + buf * (KC * AS);
        const float* ws = w_sm + buf * (KC * 128);
        // register pipeline: current k in (ac,wc), next k prefetched into (an,wn)
        float4 ac = *(const float4*)(as + rg4);
        float4 wc = *(const float4*)(ws + cg4);
#pragma unroll
        for (int k = 0; k < KC; ++k) {
            float4 an = ac, wn = wc;
            if (k + 1 < KC) {
                an = *(const float4*)(as + (k + 1) * AS + rg4);
                wn = *(const float4*)(ws + (k + 1) * 128 + cg4);
            }
            acc[0][0] = fmaf(ac.x, wc.x, acc[0][0]);
            acc[0][1] = fmaf(ac.x, wc.y, acc[0][1]);
            acc[0][2] = fmaf(ac.x, wc.z, acc[0][2]);
            acc[0][3] = fmaf(ac.x, wc.w, acc[0][3]);
            acc[1][0] = fmaf(ac.y, wc.x, acc[1][0]);
            acc[1][1] = fmaf(ac.y, wc.y, acc[1][1]);
            acc[1][2] = fmaf(ac.y, wc.z, acc[1][2]);
            acc[1][3] = fmaf(ac.y, wc.w, acc[1][3]);
            acc[2][0] = fmaf(ac.z, wc.x, acc[2][0]);
            acc[2][1] = fmaf(ac.z, wc.y, acc[2][1]);
            acc[2][2] = fmaf(ac.z, wc.z, acc[2][2]);
            acc[2][3] = fmaf(ac.z, wc.w, acc[2][3]);
            acc[3][0] = fmaf(ac.w, wc.x, acc[3][0]);
            acc[3][1] = fmaf(ac.w, wc.y, acc[3][1]);
            acc[3][2] = fmaf(ac.w, wc.z, acc[3][2]);
            acc[3][3] = fmaf(ac.w, wc.w, acc[3][3]);
            ac = an; wc = wn;
        }
        if (more) {
            buf ^= 1;
            float* asn = a_sm + buf * (KC * AS);
            float* wsn = w_sm + buf * (KC * 128);
            asn[(akk + 0) * AS + ar] = av.x;
            asn[(akk + 1) * AS + ar] = av.y;
            asn[(akk + 2) * AS + ar] = av.z;
            asn[(akk + 3) * AS + ar] = av.w;
            *(float4*)(wsn + (wk +  0) * 128 + cg4) = wv0;
            *(float4*)(wsn + (wk +  4) * 128 + cg4) = wv1;
            *(float4*)(wsn + (wk +  8) * 128 + cg4) = wv2;
            *(float4*)(wsn + (wk + 12) * 128 + cg4) = wv3;
            *(float4*)(wsn + (wk + 16) * 128 + cg4) = wv4;
            *(float4*)(wsn + (wk + 20) * 128 + cg4) = wv5;
            *(float4*)(wsn + (wk + 24) * 128 + cg4) = wv6;
            *(float4*)(wsn + (wk + 28) * 128 + cg4) = wv7;
            __syncthreads();
        }
    }
}

// gate layout local col lc = g*32 + u (g=0..3: i,f,g,o). 16 rows x 128 cols tile.
__device__ __forceinline__ void cell_update16(const float* gs, int tid, int b0, int u0,
    float* __restrict__ cd, float* __restrict__ hd,
    float* __restrict__ seqbase, size_t sbstride)
{
#pragma unroll
    for (int q = 0; q < 4; ++q) {
        int flat = tid * 4 + q;            // 0..511
        int r = flat >> 5, u = flat & 31;
        int b = b0 + r, uu = u0 + u;
        float iv = gs[r * 128 + u];
        float fv = gs[r * 128 + 32 + u];
        float gv = gs[r * 128 + 64 + u];
        float ov = gs[r * 128 + 96 + u];
        float cn = sigf(fv) * cd[b * H + uu] + sigf(iv) * tanhf(gv);
        float hn = sigf(ov) * tanhf(cn);
        cd[b * H + uu] = cn;
        hd[b * H + uu] = hn;
        if (seqbase) seqbase[(size_t)b * sbstride + uu] = hn;
    }
}

__global__ void __launch_bounds__(128) enc0_step(
    const float* __restrict__ x, const float* __restrict__ Wih,
    const float* __restrict__ Whh, const float* __restrict__ bias, int s)
{
    __shared__ float a_sm[2 * KC * AS];
    __shared__ float w_sm[2 * KC * 128];
    int tid = threadIdx.x, dir = blockIdx.z;
    int t = dir ? (T - 1 - s) : s;
    int u0 = blockIdx.x * 32, b0 = blockIdx.y * 16;
    int cg4 = (tid & 31) * 4;              // [0,128)
    int rg4 = (tid >> 5) * 4;              // [0,16)
    int wcol = (cg4 >> 5) * H + u0 + (cg4 & 31);

    const float* Wd  = Wih + dir * 2 * G4;
    const float* Whd = Whh + (size_t)dir * H * G4;
    const float* bd  = bias + dir * G4;
    float* hin  = g_eh + (s & 1) * 2 * BH + dir * BH;
    float* hout = g_eh + ((s + 1) & 1) * 2 * BH + dir * BH;
    float* cd   = g_ec + dir * BH;

    float4 bw  = *(const float4*)(bd + wcol);
    float4 wi0 = *(const float4*)(Wd + wcol);
    float4 wi1 = *(const float4*)(Wd + G4 + wcol);
    float acc[4][4];
#pragma unroll
    for (int i = 0; i < 4; ++i) {
        int b = b0 + rg4 + i;
        float x0 = x[(size_t)b * T * 2 + t * 2 + 0];
        float x1 = x[(size_t)b * T * 2 + t * 2 + 1];
        acc[i][0] = bw.x + x0 * wi0.x + x1 * wi1.x;
        acc[i][1] = bw.y + x0 * wi0.y + x1 * wi1.y;
        acc[i][2] = bw.z + x0 * wi0.z + x1 * wi1.z;
        acc[i][3] = bw.w + x0 * wi0.w + x1 * wi1.w;
    }
    lstm_tile_acc(acc, hin + (size_t)b0 * H, H, H, Whd, G4, wcol, a_sm, w_sm, tid, rg4, cg4);
    __syncthreads();
#pragma unroll
    for (int i = 0; i < 4; ++i)
#pragma unroll
        for (int j = 0; j < 4; ++j)
            w_sm[(rg4 + i) * 128 + cg4 + j] = acc[i][j];
    __syncthreads();
    cell_update16(w_sm, tid, b0, u0, cd, hout,
                  g_l0 + (size_t)t * B * E2 + dir * H, E2);
}

__global__ void __launch_bounds__(128) enc1_step(
    const float* __restrict__ Wih, const float* __restrict__ Whh,
    const float* __restrict__ bias, int s)
{
    __shared__ float a_sm[2 * KC * AS];
    __shared__ float w_sm[2 * KC * 128];
    int tid = threadIdx.x, dir = blockIdx.z;
    int t = dir ? (T - 1 - s) : s;
    int u0 = blockIdx.x * 32, b0 = blockIdx.y * 16;
    int cg4 = (tid & 31) * 4;
    int rg4 = (tid >> 5) * 4;
    int wcol = (cg4 >> 5) * H + u0 + (cg4 & 31);

    const float* Wd  = Wih + (size_t)dir * E2 * G4;
    const float* Whd = Whh + (size_t)dir * H * G4;
    const float* bd  = bias + dir * G4;
    float* hin  = g_eh + (s & 1) * 2 * BH + dir * BH;
    float* hout = g_eh + ((s + 1) & 1) * 2 * BH + dir * BH;
    float* cd   = g_ec + dir * BH;

    float4 bw = *(const float4*)(bd + wcol);
    float acc[4][4];
#pragma unroll
    for (int i = 0; i < 4; ++i) {
        acc[i][0] = bw.x; acc[i][1] = bw.y; acc[i][2] = bw.z; acc[i][3] = bw.w;
    }
    lstm_tile_acc(acc, g_l0 + (size_t)t * B * E2 + (size_t)b0 * E2, E2, E2, Wd, G4, wcol,
                  a_sm, w_sm, tid, rg4, cg4);
    lstm_tile_acc(acc, hin + (size_t)b0 * H, H, H, Whd, G4, wcol, a_sm, w_sm, tid, rg4, cg4);
    __syncthreads();
#pragma unroll
    for (int i = 0; i < 4; ++i)
#pragma unroll
        for (int j = 0; j < 4; ++j)
            w_sm[(rg4 + i) * 128 + cg4 + j] = acc[i][j];
    __syncthreads();
    cell_update16(w_sm, tid, b0, u0, cd, hout,
                  g_enc + (size_t)t * E2 + dir * H, (size_t)T * E2);
}

__global__ void __launch_bounds__(128) dec_step(
    const float* __restrict__ Wih, const float* __restrict__ Whh,
    const float* __restrict__ bias, int layer, int s)
{
    __shared__ float a_sm[2 * KC * AS];
    __shared__ float w_sm[2 * KC * 128];
    int tid = threadIdx.x;
    int u0 = blockIdx.x * 32, b0 = blockIdx.y * 16;
    int cg4 = (tid & 31) * 4;
    int rg4 = (tid >> 5) * 4;
    int wcol = (cg4 >> 5) * H + u0 + (cg4 & 31);

    const float* Wd  = Wih + (size_t)layer * H * G4;
    const float* Whd = Whh + (size_t)layer * H * G4;
    const float* bd  = bias + layer * G4;
    const float* A1  = (layer == 0) ? g_din : (g_dh + ((s + 1) & 1) * 2 * BH);
    float* hin  = g_dh + (s & 1) * 2 * BH + layer * BH;
    float* hout = g_dh + ((s + 1) & 1) * 2 * BH + layer * BH;
    float* cd   = g_dc + layer * BH;

    float4 bw = *(const float4*)(bd + wcol);
    float acc[4][4];
#pragma unroll
    for (int i = 0; i < 4; ++i) {
        acc[i][0] = bw.x; acc[i][1] = bw.y; acc[i][2] = bw.z; acc[i][3] = bw.w;
    }
    lstm_tile_acc(acc, A1 + (size_t)b0 * H, H, H, Wd, G4, wcol, a_sm, w_sm, tid, rg4, cg4);
    lstm_tile_acc(acc, hin + (size_t)b0 * H, H, H, Whd, G4, wcol, a_sm, w_sm, tid, rg4, cg4);
    __syncthreads();
#pragma unroll
    for (int i = 0; i < 4; ++i)
#pragma unroll
        for (int j = 0; j < 4; ++j)
            w_sm[(rg4 + i) * 128 + cg4 + j] = acc[i][j];
    __syncthreads();
    cell_update16(w_sm, tid, b0, u0, cd, hout, nullptr, 0);
}

// ================= small GEMMs (query/comb/logits): 128-thread 32x64 tile =================
__device__ __forceinline__ void tile_acc128(float acc[4][4],
    const float* __restrict__ A, int lda, int K,
    const float* __restrict__ W, int ldw, int wcol,
    float* a_sm, float* w_sm, int tid, int rg4, int cg4)
{
    const int ar = tid >> 2;
    const int ak = (tid & 3) << 2;
    const int wk = tid >> 4;
    float4 av  = *(const float4*)(A + (size_t)ar * lda + ak);
    float4 wv0 = *(const float4*)(W + (size_t)wk * ldw + wcol);
    float4 wv1 = *(const float4*)(W + (size_t)(wk + 8) * ldw + wcol);
    __syncthreads();
    a_sm[(ak + 0) * 32 + ar] = av.x;
    a_sm[(ak + 1) * 32 + ar] = av.y;
    a_sm[(ak + 2) * 32 + ar] = av.z;
    a_sm[(ak + 3) * 32 + ar] = av.w;
    *(float4*)(w_sm + wk * 64 + cg4)       = wv0;
    *(float4*)(w_sm + (wk + 8) * 64 + cg4) = wv1;
    __syncthreads();
    int buf = 0;
    for (int kt = 0; kt < K; kt += 16) {
        const bool more = (kt + 16 < K);
        if (more) {
            av  = *(const float4*)(A + (size_t)ar * lda + kt + 16 + ak);
            wv0 = *(const float4*)(W + (size_t)(kt + 16 + wk) * ldw + wcol);
            wv1 = *(const float4*)(W + (size_t)(kt + 24 + wk) * ldw + wcol);
        }
        const float* as = a_sm + buf * (16 * 32);
        const float* ws = w_sm + buf * (16 * 64);
        float4 ac = *(const float4*)(as + rg4);
        float4 wc = *(const float4*)(ws + cg4);
#pragma unroll
        for (int k = 0; k < 16; ++k) {
            float4 an = ac, wn = wc;
            if (k + 1 < 16) {
                an = *(const float4*)(as + (k + 1) * 32 + rg4);
                wn = *(const float4*)(ws + (k + 1) * 64 + cg4);
            }
            acc[0][0] = fmaf(ac.x, wc.x, acc[0][0]);
            acc[0][1] = fmaf(ac.x, wc.y, acc[0][1]);
            acc[0][2] = fmaf(ac.x, wc.z, acc[0][2]);
            acc[0][3] = fmaf(ac.x, wc.w, acc[0][3]);
            acc[1][0] = fmaf(ac.y, wc.x, acc[1][0]);
            acc[1][1] = fmaf(ac.y, wc.y, acc[1][1]);
            acc[1][2] = fmaf(ac.y, wc.z, acc[1][2]);
            acc[1][3] = fmaf(ac.y, wc.w, acc[1][3]);
            acc[2][0] = fmaf(ac.z, wc.x, acc[2][0]);
            acc[2][1] = fmaf(ac.z, wc.y, acc[2][1]);
            acc[2][2] = fmaf(ac.z, wc.z, acc[2][2]);
            acc[2][3] = fmaf(ac.z, wc.w, acc[2][3]);
            acc[3][0] = fmaf(ac.w, wc.x, acc[3][0]);
            acc[3][1] = fmaf(ac.w, wc.y, acc[3][1]);
            acc[3][2] = fmaf(ac.w, wc.z, acc[3][2]);
            acc[3][3] = fmaf(ac.w, wc.w, acc[3][3]);
            ac = an; wc = wn;
        }
        if (more) {
            buf ^= 1;
            float* asn = a_sm + buf * (16 * 32);
            float* wsn = w_sm + buf * (16 * 64);
            asn[(ak + 0) * 32 + ar] = av.x;
            asn[(ak + 1) * 32 + ar] = av.y;
            asn[(ak + 2) * 32 + ar] = av.z;
            asn[(ak + 3) * 32 + ar] = av.w;
            *(float4*)(wsn + wk * 64 + cg4)       = wv0;
            *(float4*)(wsn + (wk + 8) * 64 + cg4) = wv1;
            __syncthreads();
        }
    }
}

__device__ __forceinline__ void gemm_core(
    const float* A1, int lda1, int K1, const float* W1,
    const float* A2, int lda2, int K2, const float* W2,
    int ldw, const float* bias, float* C, int ldc,
    float* a_sm, float* w_sm)
{
    int tid = threadIdx.x;
    int n0 = blockIdx.x * 64, b0 = blockIdx.y * 32;
    int cg4 = (tid & 15) * 4, rg4 = (tid >> 4) * 4;
    int wcol = n0 + cg4;
    float4 bw = *(const float4*)(bias + wcol);
    float acc[4][4];
#pragma unroll
    for (int i = 0; i < 4; ++i) {
        acc[i][0] = bw.x; acc[i][1] = bw.y; acc[i][2] = bw.z; acc[i][3] = bw.w;
    }
    tile_acc128(acc, A1 + (size_t)b0 * lda1, lda1, K1, W1, ldw, wcol, a_sm, w_sm, tid, rg4, cg4);
    if (K2 > 0)
        tile_acc128(acc, A2 + (size_t)b0 * lda2, lda2, K2, W2, ldw, wcol, a_sm, w_sm, tid, rg4, cg4);
#pragma unroll
    for (int i = 0; i < 4; ++i)
        *(float4*)(C + (size_t)(b0 + rg4 + i) * ldc + wcol) =
            make_float4(acc[i][0], acc[i][1], acc[i][2], acc[i][3]);
}

__global__ void __launch_bounds__(128) query_kernel(const float* __restrict__ Wq,
                                                    const float* __restrict__ bq, int s)
{
    __shared__ float a_sm[2 * 16 * 32], w_sm[2 * 16 * 64];
    const float* h1 = g_dh + ((s + 1) & 1) * 2 * BH + BH;
    gemm_core(h1, H, H, Wq, nullptr, 0, 0, nullptr, E2, bq, g_q, E2, a_sm, w_sm);
}

__global__ void __launch_bounds__(128) comb_kernel(const float* __restrict__ Wc,
                                                   const float* __restrict__ bc, int s)
{
    __shared__ float a_sm[2 * 16 * 32], w_sm[2 * 16 * 64];
    const float* h1 = g_dh + ((s + 1) & 1) * 2 * BH + BH;
    gemm_core(h1, H, H, Wc, g_cx, E2, E2, Wc + (size_t)H * H, H, bc, g_cb, H, a_sm, w_sm);
}

__global__ void __launch_bounds__(128) logits_kernel(const float* __restrict__ Wf,
                                                     const float* __restrict__ bf,
                                                     float* __restrict__ out, int s)
{
    __shared__ float a_sm[2 * 16 * 32], w_sm[2 * 16 * 64];
    gemm_core(g_cb, H, H, Wf, nullptr, 0, 0, nullptr, V, bf,
              out + (size_t)s * V, LW * V, a_sm, w_sm);
}

__global__ void __launch_bounds__(256) attn_kernel(float* __restrict__ out, int step)
{
    __shared__ float qs[E2];
    __shared__ float sc[T];
    __shared__ float red[8];
    int b = blockIdx.x, tid = threadIdx.x;
    const float* eb = g_enc + (size_t)b * T * E2;
    for (int j = tid; j < E2; j += 256) qs[j] = g_q[b * E2 + j];
    __syncthreads();
    int warp = tid >> 5, lane = tid & 31;
    for (int t = warp; t < T; t += 8) {
        const float* er = eb + (size_t)t * E2;
        float acc = 0.f;
#pragma unroll 8
        for (int j = lane; j < E2; j += 32) acc += er[j] * qs[j];
#pragma unroll
        for (int o = 16; o; o >>= 1) acc += __shfl_xor_sync(0xffffffffu, acc, o);
        if (lane == 0) sc[t] = acc;
    }
    __syncthreads();
    float v = sc[tid];
    float m = v;
#pragma unroll
    for (int o = 16; o; o >>= 1) m = fmaxf(m, __shfl_xor_sync(0xffffffffu, m, o));
    if (lane == 0) red[warp] = m;
    __syncthreads();
    float bm = red[0];
#pragma unroll
    for (int w = 1; w < 8; ++w) bm = fmaxf(bm, red[w]);
    float e = expf(v - bm);
    float ssum = e;
#pragma unroll
    for (int o = 16; o; o >>= 1) ssum += __shfl_xor_sync(0xffffffffu, ssum, o);
    __syncthreads();
    if (lane == 0) red[warp] = ssum;
    __syncthreads();
    float tot = 0.f;
#pragma unroll
    for (int w = 0; w < 8; ++w) tot += red[w];
    float p = e / tot;
    sc[tid] = p;
    out[OUT_ATT + (size_t)b * T * LW + (size_t)tid * LW + step] = p;
    __syncthreads();
    float a0 = 0.f, a1 = 0.f, a2 = 0.f, a3 = 0.f;
    for (int t = 0; t < T; ++t) {
        float pt = sc[t];
        const float* er = eb + (size_t)t * E2;
        a0 = fmaf(pt, er[tid], a0);
        a1 = fmaf(pt, er[tid + 256], a1);
        a2 = fmaf(pt, er[tid + 512], a2);
        a3 = fmaf(pt, er[tid + 768], a3);
    }
    g_cx[b * E2 + tid]       = a0;
    g_cx[b * E2 + tid + 256] = a1;
    g_cx[b * E2 + tid + 512] = a2;
    g_cx[b * E2 + tid + 768] = a3;
}

__global__ void argmax_kernel(const float* __restrict__ out, int step)
{
    int b = blockIdx.x, tid = threadIdx.x;   // 128 threads = V
    float v = out[(size_t)b * LW * V + (size_t)step * V + tid];
    int idx = tid;
#pragma unroll
    for (int o = 16; o; o >>= 1) {
        float ov = __shfl_xor_sync(0xffffffffu, v, o);
        int oi = __shfl_xor_sync(0xffffffffu, idx, o);
        if (ov > v || (ov == v && oi < idx)) { v = ov; idx = oi; }
    }
    __shared__ float sv[4];
    __shared__ int si[4];
    if ((tid & 31) == 0) { sv[tid >> 5] = v; si[tid >> 5] = idx; }
    __syncthreads();
    if (tid == 0) {
#pragma unroll
        for (int w = 1; w < 4; ++w)
            if (sv[w] > v || (sv[w] == v && si[w] < idx)) { v = sv[w]; idx = si[w]; }
        g_tok[b] = idx;
    }
}

__global__ void gather_emb(const float* __restrict__ emb)
{
    g_din[blockIdx.x * H + threadIdx.x] = emb[(size_t)g_tok[blockIdx.x] * H + threadIdx.x];
}

__global__ void init_tok() { g_tok[threadIdx.x] = 1; }   // SOS = 1

__global__ void zero_enc()
{
    int i = blockIdx.x * blockDim.x + threadIdx.x;
    if (i < 4 * BH) g_eh[i] = 0.f;
    if (i < 2 * BH) g_ec[i] = 0.f;
}

__global__ void sum_states(int l)
{
    int i = blockIdx.x * blockDim.x + threadIdx.x;
    if (i < BH) {
        g_dh[l * BH + i] = g_eh[i] + g_eh[BH + i];   // phase0 holds finals after T steps
        g_dc[l * BH + i] = g_ec[i] + g_ec[BH + i];
    }
}

__global__ void final_copy(float* __restrict__ out)
{
    int i = blockIdx.x * blockDim.x + threadIdx.x;
    if (i < NL * BH) {
        out[OUT_HF + i] = g_dh[i];   // phase 0 after 32 decoder steps
        out[OUT_CF + i] = g_dc[i];
    }
}

extern "C" void kernel_launch(void* const* d_in, const int* in_sizes, int n_in,
                              void* d_out, int out_size)
{
    const float* x     = (const float*)d_in[0];
    const float* e0Wih = (const float*)d_in[1];
    const float* e0Whh = (const float*)d_in[2];
    const float* e0b   = (const float*)d_in[3];
    const float* e1Wih = (const float*)d_in[4];
    const float* e1Whh = (const float*)d_in[5];
    const float* e1b   = (const float*)d_in[6];
    const float* dWih  = (const float*)d_in[7];
    const float* dWhh  = (const float*)d_in[8];
    const float* db    = (const float*)d_in[9];
    const float* emb   = (const float*)d_in[10];
    const float* Wq    = (const float*)d_in[11];
    const float* bq    = (const float*)d_in[12];
    const float* Wc    = (const float*)d_in[13];
    const float* bc    = (const float*)d_in[14];
    const float* Wf    = (const float*)d_in[15];
    const float* bf    = (const float*)d_in[16];
    float* out = (float*)d_out;

    dim3 gL(16, 8, 2), gD(16, 8, 1);

    zero_enc<<<(4 * BH + 255) / 256, 256>>>();
    for (int s = 0; s < T; ++s)
        enc0_step<<<gL, 128>>>(x, e0Wih, e0Whh, e0b, s);
    sum_states<<<256, 256>>>(0);

    zero_enc<<<(4 * BH + 255) / 256, 256>>>();
    for (int s = 0; s < T; ++s)
        enc1_step<<<gL, 128>>>(e1Wih, e1Whh, e1b, s);
    sum_states<<<256, 256>>>(1);

    init_tok<<<1, B>>>();
    for (int s = 0; s < LW; ++s) {
        gather_emb<<<B, H>>>(emb);
        dec_step<<<gD, 128>>>(dWih, dWhh, db, 0, s);
        dec_step<<<gD, 128>>>(dWih, dWhh, db, 1, s);
        query_kernel<<<dim3(16, 4), 128>>>(Wq, bq, s);
        attn_kernel<<<B, 256>>>(out, s);
        comb_kernel<<<dim3(8, 4), 128>>>(Wc, bc, s);
        logits_kernel<<<dim3(2, 4), 128>>>(Wf, bf, out, s);
        argmax_kernel<<<B, 128>>>(out, s);
    }
    final_copy<<<512, 256>>>(out);
}

// round 13
// speedup vs baseline: 1.1200x; 1.1200x over previous
#include <cuda_runtime.h>
#include <math.h>

static constexpr int H  = 512;
static constexpr int G4 = 2048;
static constexpr int B  = 128;
static constexpr int T  = 256;
static constexpr int V  = 128;
static constexpr int LW = 32;
static constexpr int NL = 2;
static constexpr int BH = B * H;
static constexpr int E2 = 2 * H;
static constexpr int KC = 32;       // k-chunk for LSTM tiles
static constexpr int AS = 20;       // a_sm row stride (pad)

static constexpr long OUT_HF  = (long)B * LW * V;
static constexpr long OUT_CF  = OUT_HF + (long)NL * BH;
static constexpr long OUT_ATT = OUT_CF + (long)NL * BH;

// ---- scratch (device globals; no runtime allocation) ----
__device__ float g_l0[(size_t)T * B * E2];    // layer0 out [t][b][2H]
__device__ float g_pre[(size_t)T * B * 4096]; // enc1 input-proj gates [t][b][dir*2048+col]
__device__ float g_enc[(size_t)B * T * E2];   // encoder out [b][t][2H]
__device__ float g_eh[2 * 2 * BH];            // enc h [phase][dir][B][H]
__device__ float g_ec[2 * BH];                // enc c [dir][B][H]
__device__ float g_dh[2 * 2 * BH];            // dec h [phase][layer][B][H]
__device__ float g_dc[2 * BH];                // dec c [layer][B][H]
__device__ float g_din[BH];
__device__ float g_q[B * E2];
__device__ float g_cx[B * E2];
__device__ float g_cb[BH];
__device__ int   g_tok[B];

__device__ __forceinline__ float sigf(float x) { return 1.0f / (1.0f + expf(-x)); }

#define FMA16(ac, wc)                                   \
    acc[0][0] = fmaf(ac.x, wc.x, acc[0][0]);            \
    acc[0][1] = fmaf(ac.x, wc.y, acc[0][1]);            \
    acc[0][2] = fmaf(ac.x, wc.z, acc[0][2]);            \
    acc[0][3] = fmaf(ac.x, wc.w, acc[0][3]);            \
    acc[1][0] = fmaf(ac.y, wc.x, acc[1][0]);            \
    acc[1][1] = fmaf(ac.y, wc.y, acc[1][1]);            \
    acc[1][2] = fmaf(ac.y, wc.z, acc[1][2]);            \
    acc[1][3] = fmaf(ac.y, wc.w, acc[1][3]);            \
    acc[2][0] = fmaf(ac.z, wc.x, acc[2][0]);            \
    acc[2][1] = fmaf(ac.z, wc.y, acc[2][1]);            \
    acc[2][2] = fmaf(ac.z, wc.z, acc[2][2]);            \
    acc[2][3] = fmaf(ac.z, wc.w, acc[2][3]);            \
    acc[3][0] = fmaf(ac.w, wc.x, acc[3][0]);            \
    acc[3][1] = fmaf(ac.w, wc.y, acc[3][1]);            \
    acc[3][2] = fmaf(ac.w, wc.z, acc[3][2]);            \
    acc[3][3] = fmaf(ac.w, wc.w, acc[3][3]);

// ========== LSTM GEMM: 16 rows x 128 gate-cols, 128 threads, 4x4/thread ==========
__device__ __forceinline__ void lstm_tile_acc(float acc[4][4],
    const float* __restrict__ A, int lda, int K,
    const float* __restrict__ W, int ldw, int wcol,
    float* a_sm, float* w_sm, int tid, int rg4, int cg4)
{
    const int ar  = tid & 15;
    const int akk = (tid >> 4) * 4;
    const int wk  = tid >> 5;
    float4 av, wv0, wv1, wv2, wv3, wv4, wv5, wv6, wv7;
    av  = *(const float4*)(A + (size_t)ar * lda + akk);
    wv0 = *(const float4*)(W + (size_t)(wk +  0) * ldw + wcol);
    wv1 = *(const float4*)(W + (size_t)(wk +  4) * ldw + wcol);
    wv2 = *(const float4*)(W + (size_t)(wk +  8) * ldw + wcol);
    wv3 = *(const float4*)(W + (size_t)(wk + 12) * ldw + wcol);
    wv4 = *(const float4*)(W + (size_t)(wk + 16) * ldw + wcol);
    wv5 = *(const float4*)(W + (size_t)(wk + 20) * ldw + wcol);
    wv6 = *(const float4*)(W + (size_t)(wk + 24) * ldw + wcol);
    wv7 = *(const float4*)(W + (size_t)(wk + 28) * ldw + wcol);
    __syncthreads();
    a_sm[(akk + 0) * AS + ar] = av.x;
    a_sm[(akk + 1) * AS + ar] = av.y;
    a_sm[(akk + 2) * AS + ar] = av.z;
    a_sm[(akk + 3) * AS + ar] = av.w;
    *(float4*)(w_sm + (wk +  0) * 128 + cg4) = wv0;
    *(float4*)(w_sm + (wk +  4) * 128 + cg4) = wv1;
    *(float4*)(w_sm + (wk +  8) * 128 + cg4) = wv2;
    *(float4*)(w_sm + (wk + 12) * 128 + cg4) = wv3;
    *(float4*)(w_sm + (wk + 16) * 128 + cg4) = wv4;
    *(float4*)(w_sm + (wk + 20) * 128 + cg4) = wv5;
    *(float4*)(w_sm + (wk + 24) * 128 + cg4) = wv6;
    *(float4*)(w_sm + (wk + 28) * 128 + cg4) = wv7;
    __syncthreads();
    int buf = 0;
    for (int kt = 0; kt < K; kt += KC) {
        const bool more = (kt + KC < K);
        if (more) {
            const float* An = A + (size_t)ar * lda + kt + KC;
            const float* Wn = W + (size_t)(kt + KC) * ldw + wcol;
            av  = *(const float4*)(An + akk);
            wv0 = *(const float4*)(Wn + (size_t)(wk +  0) * ldw);
            wv1 = *(const float4*)(Wn + (size_t)(wk +  4) * ldw);
            wv2 = *(const float4*)(Wn + (size_t)(wk +  8) * ldw);
            wv3 = *(const float4*)(Wn + (size_t)(wk + 12) * ldw);
            wv4 = *(const float4*)(Wn + (size_t)(wk + 16) * ldw);
            wv5 = *(const float4*)(Wn + (size_t)(wk + 20) * ldw);
            wv6 = *(const float4*)(Wn + (size_t)(wk + 24) * ldw);
            wv7 = *(const float4*)(Wn + (size_t)(wk + 28) * ldw);
        }
        const float* as = a_sm + buf * (KC * AS);
        const float* ws = w_sm + buf * (KC * 128);
        float4 ac = *(const float4*)(as + rg4);
        float4 wc = *(const float4*)(ws + cg4);
#pragma unroll
        for (int k = 0; k < KC; ++k) {
            float4 an = ac, wn = wc;
            if (k + 1 < KC) {
                an = *(const float4*)(as + (k + 1) * AS + rg4);
                wn = *(const float4*)(ws + (k + 1) * 128 + cg4);
            }
            FMA16(ac, wc)
            ac = an; wc = wn;
        }
        if (more) {
            buf ^= 1;
            float* asn = a_sm + buf * (KC * AS);
            float* wsn = w_sm + buf * (KC * 128);
            asn[(akk + 0) * AS + ar] = av.x;
            asn[(akk + 1) * AS + ar] = av.y;
            asn[(akk + 2) * AS + ar] = av.z;
            asn[(akk + 3) * AS + ar] = av.w;
            *(float4*)(wsn + (wk +  0) * 128 + cg4) = wv0;
            *(float4*)(wsn + (wk +  4) * 128 + cg4) = wv1;
            *(float4*)(wsn + (wk +  8) * 128 + cg4) = wv2;
            *(float4*)(wsn + (wk + 12) * 128 + cg4) = wv3;
            *(float4*)(wsn + (wk + 16) * 128 + cg4) = wv4;
            *(float4*)(wsn + (wk + 20) * 128 + cg4) = wv5;
            *(float4*)(wsn + (wk + 24) * 128 + cg4) = wv6;
            *(float4*)(wsn + (wk + 28) * 128 + cg4) = wv7;
            __syncthreads();
        }
    }
}

// gate layout local col lc = g*32 + u (g=0..3: i,f,g,o). 16 rows x 128 cols tile.
__device__ __forceinline__ void cell_update16(const float* gs, int tid, int b0, int u0,
    float* __restrict__ cd, float* __restrict__ hd,
    float* __restrict__ seqbase, size_t sbstride)
{
#pragma unroll
    for (int q = 0; q < 4; ++q) {
        int flat = tid * 4 + q;
        int r = flat >> 5, u = flat & 31;
        int b = b0 + r, uu = u0 + u;
        float iv = gs[r * 128 + u];
        float fv = gs[r * 128 + 32 + u];
        float gv = gs[r * 128 + 64 + u];
        float ov = gs[r * 128 + 96 + u];
        float cn = sigf(fv) * cd[b * H + uu] + sigf(iv) * tanhf(gv);
        float hn = sigf(ov) * tanhf(cn);
        cd[b * H + uu] = cn;
        hd[b * H + uu] = hn;
        if (seqbase) seqbase[(size_t)b * sbstride + uu] = hn;
    }
}

__global__ void __launch_bounds__(128) enc0_step(
    const float* __restrict__ x, const float* __restrict__ Wih,
    const float* __restrict__ Whh, const float* __restrict__ bias, int s)
{
    __shared__ float a_sm[2 * KC * AS];
    __shared__ float w_sm[2 * KC * 128];
    int tid = threadIdx.x, dir = blockIdx.z;
    int t = dir ? (T - 1 - s) : s;
    int u0 = blockIdx.x * 32, b0 = blockIdx.y * 16;
    int cg4 = (tid & 31) * 4;
    int rg4 = (tid >> 5) * 4;
    int wcol = (cg4 >> 5) * H + u0 + (cg4 & 31);

    const float* Wd  = Wih + dir * 2 * G4;
    const float* Whd = Whh + (size_t)dir * H * G4;
    const float* bd  = bias + dir * G4;
    float* hin  = g_eh + (s & 1) * 2 * BH + dir * BH;
    float* hout = g_eh + ((s + 1) & 1) * 2 * BH + dir * BH;
    float* cd   = g_ec + dir * BH;

    float4 bw  = *(const float4*)(bd + wcol);
    float4 wi0 = *(const float4*)(Wd + wcol);
    float4 wi1 = *(const float4*)(Wd + G4 + wcol);
    float acc[4][4];
#pragma unroll
    for (int i = 0; i < 4; ++i) {
        int b = b0 + rg4 + i;
        float x0 = x[(size_t)b * T * 2 + t * 2 + 0];
        float x1 = x[(size_t)b * T * 2 + t * 2 + 1];
        acc[i][0] = bw.x + x0 * wi0.x + x1 * wi1.x;
        acc[i][1] = bw.y + x0 * wi0.y + x1 * wi1.y;
        acc[i][2] = bw.z + x0 * wi0.z + x1 * wi1.z;
        acc[i][3] = bw.w + x0 * wi0.w + x1 * wi1.w;
    }
    lstm_tile_acc(acc, hin + (size_t)b0 * H, H, H, Whd, G4, wcol, a_sm, w_sm, tid, rg4, cg4);
    __syncthreads();
#pragma unroll
    for (int i = 0; i < 4; ++i)
#pragma unroll
        for (int j = 0; j < 4; ++j)
            w_sm[(rg4 + i) * 128 + cg4 + j] = acc[i][j];
    __syncthreads();
    cell_update16(w_sm, tid, b0, u0, cd, hout,
                  g_l0 + (size_t)t * B * E2 + dir * H, E2);
}

// ===== pre_gemm: g_pre[t*B+b][dir*2048+col] = bias + g_l0[t][b][:] @ Wih[dir] =====
// M=32768, N=4096, K=1024. 64x64 tile, 256 threads, 4x4/thread.
__global__ void __launch_bounds__(256) pre_gemm(
    const float* __restrict__ Wih, const float* __restrict__ bias)
{
    __shared__ float a_sm[2 * 16 * 64];
    __shared__ float w_sm[2 * 16 * 64];
    int tid = threadIdx.x;
    int n0 = blockIdx.x * 64;
    int m0 = blockIdx.y * 64;
    int dir  = n0 >> 11;
    int col0 = n0 & 2047;
    const float* W = Wih + (size_t)dir * E2 * G4 + col0;   // [1024][2048] slice
    const float* A = g_l0 + (size_t)m0 * E2;               // rows of 1024

    int cg4 = (tid & 15) * 4;          // col in tile
    int rg4 = (tid >> 4) * 4;          // row in tile
    const int ar = tid & 63;           // A loader row
    const int ak = (tid >> 6) * 4;     // A loader k-group
    const int wk = tid >> 4;           // W loader k (0..15)

    float4 bw = *(const float4*)(bias + dir * G4 + col0 + cg4);
    float acc[4][4];
#pragma unroll
    for (int i = 0; i < 4; ++i) {
        acc[i][0] = bw.x; acc[i][1] = bw.y; acc[i][2] = bw.z; acc[i][3] = bw.w;
    }

    float4 av = *(const float4*)(A + (size_t)ar * E2 + ak);
    float4 wv = *(const float4*)(W + (size_t)wk * G4 + cg4);
    a_sm[(ak + 0) * 64 + ar] = av.x;
    a_sm[(ak + 1) * 64 + ar] = av.y;
    a_sm[(ak + 2) * 64 + ar] = av.z;
    a_sm[(ak + 3) * 64 + ar] = av.w;
    *(float4*)(w_sm + wk * 64 + cg4) = wv;
    __syncthreads();
    int buf = 0;
    for (int kt = 0; kt < E2; kt += 16) {
        const bool more = (kt + 16 < E2);
        if (more) {
            av = *(const float4*)(A + (size_t)ar * E2 + kt + 16 + ak);
            wv = *(const float4*)(W + (size_t)(kt + 16 + wk) * G4 + cg4);
        }
        const float* as = a_sm + buf * (16 * 64);
        const float* ws = w_sm + buf * (16 * 64);
        float4 ac = *(const float4*)(as + rg4);
        float4 wc = *(const float4*)(ws + cg4);
#pragma unroll
        for (int k = 0; k < 16; ++k) {
            float4 an = ac, wn = wc;
            if (k + 1 < 16) {
                an = *(const float4*)(as + (k + 1) * 64 + rg4);
                wn = *(const float4*)(ws + (k + 1) * 64 + cg4);
            }
            FMA16(ac, wc)
            ac = an; wc = wn;
        }
        if (more) {
            buf ^= 1;
            float* asn = a_sm + buf * (16 * 64);
            float* wsn = w_sm + buf * (16 * 64);
            asn[(ak + 0) * 64 + ar] = av.x;
            asn[(ak + 1) * 64 + ar] = av.y;
            asn[(ak + 2) * 64 + ar] = av.z;
            asn[(ak + 3) * 64 + ar] = av.w;
            *(float4*)(wsn + wk * 64 + cg4) = wv;
            __syncthreads();
        }
    }
    float* C = g_pre + (size_t)m0 * 4096 + n0;
#pragma unroll
    for (int i = 0; i < 4; ++i)
        *(float4*)(C + (size_t)(rg4 + i) * 4096 + cg4) =
            make_float4(acc[i][0], acc[i][1], acc[i][2], acc[i][3]);
}

// enc1 sequential step: only the recurrent K=512 GEMM; input gates preloaded.
__global__ void __launch_bounds__(128) enc1_step(
    const float* __restrict__ Whh, int s)
{
    __shared__ float a_sm[2 * KC * AS];
    __shared__ float w_sm[2 * KC * 128];
    int tid = threadIdx.x, dir = blockIdx.z;
    int t = dir ? (T - 1 - s) : s;
    int u0 = blockIdx.x * 32, b0 = blockIdx.y * 16;
    int cg4 = (tid & 31) * 4;
    int rg4 = (tid >> 5) * 4;
    int wcol = (cg4 >> 5) * H + u0 + (cg4 & 31);

    const float* Whd = Whh + (size_t)dir * H * G4;
    float* hin  = g_eh + (s & 1) * 2 * BH + dir * BH;
    float* hout = g_eh + ((s + 1) & 1) * 2 * BH + dir * BH;
    float* cd   = g_ec + dir * BH;

    const float* pre = g_pre + ((size_t)t * B + b0) * 4096 + dir * G4;
    float acc[4][4];
#pragma unroll
    for (int i = 0; i < 4; ++i) {
        float4 pv = *(const float4*)(pre + (size_t)(rg4 + i) * 4096 + wcol);
        acc[i][0] = pv.x; acc[i][1] = pv.y; acc[i][2] = pv.z; acc[i][3] = pv.w;
    }
    lstm_tile_acc(acc, hin + (size_t)b0 * H, H, H, Whd, G4, wcol, a_sm, w_sm, tid, rg4, cg4);
    __syncthreads();
#pragma unroll
    for (int i = 0; i < 4; ++i)
#pragma unroll
        for (int j = 0; j < 4; ++j)
            w_sm[(rg4 + i) * 128 + cg4 + j] = acc[i][j];
    __syncthreads();
    cell_update16(w_sm, tid, b0, u0, cd, hout,
                  g_enc + (size_t)t * E2 + dir * H, (size_t)T * E2);
}

__global__ void __launch_bounds__(128) dec_step(
    const float* __restrict__ Wih, const float* __restrict__ Whh,
    const float* __restrict__ bias, int layer, int s)
{
    __shared__ float a_sm[2 * KC * AS];
    __shared__ float w_sm[2 * KC * 128];
    int tid = threadIdx.x;
    int u0 = blockIdx.x * 32, b0 = blockIdx.y * 16;
    int cg4 = (tid & 31) * 4;
    int rg4 = (tid >> 5) * 4;
    int wcol = (cg4 >> 5) * H + u0 + (cg4 & 31);

    const float* Wd  = Wih + (size_t)layer * H * G4;
    const float* Whd = Whh + (size_t)layer * H * G4;
    const float* bd  = bias + layer * G4;
    const float* A1  = (layer == 0) ? g_din : (g_dh + ((s + 1) & 1) * 2 * BH);
    float* hin  = g_dh + (s & 1) * 2 * BH + layer * BH;
    float* hout = g_dh + ((s + 1) & 1) * 2 * BH + layer * BH;
    float* cd   = g_dc + layer * BH;

    float4 bw = *(const float4*)(bd + wcol);
    float acc[4][4];
#pragma unroll
    for (int i = 0; i < 4; ++i) {
        acc[i][0] = bw.x; acc[i][1] = bw.y; acc[i][2] = bw.z; acc[i][3] = bw.w;
    }
    lstm_tile_acc(acc, A1 + (size_t)b0 * H, H, H, Wd, G4, wcol, a_sm, w_sm, tid, rg4, cg4);
    lstm_tile_acc(acc, hin + (size_t)b0 * H, H, H, Whd, G4, wcol, a_sm, w_sm, tid, rg4, cg4);
    __syncthreads();
#pragma unroll
    for (int i = 0; i < 4; ++i)
#pragma unroll
        for (int j = 0; j < 4; ++j)
            w_sm[(rg4 + i) * 128 + cg4 + j] = acc[i][j];
    __syncthreads();
    cell_update16(w_sm, tid, b0, u0, cd, hout, nullptr, 0);
}

// ================= small GEMMs (query/comb/logits): 128-thread 32x64 tile =================
__device__ __forceinline__ void tile_acc128(float acc[4][4],
    const float* __restrict__ A, int lda, int K,
    const float* __restrict__ W, int ldw, int wcol,
    float* a_sm, float* w_sm, int tid, int rg4, int cg4)
{
    const int ar = tid >> 2;
    const int ak = (tid & 3) << 2;
    const int wk = tid >> 4;
    float4 av  = *(const float4*)(A + (size_t)ar * lda + ak);
    float4 wv0 = *(const float4*)(W + (size_t)wk * ldw + wcol);
    float4 wv1 = *(const float4*)(W + (size_t)(wk + 8) * ldw + wcol);
    __syncthreads();
    a_sm[(ak + 0) * 32 + ar] = av.x;
    a_sm[(ak + 1) * 32 + ar] = av.y;
    a_sm[(ak + 2) * 32 + ar] = av.z;
    a_sm[(ak + 3) * 32 + ar] = av.w;
    *(float4*)(w_sm + wk * 64 + cg4)       = wv0;
    *(float4*)(w_sm + (wk + 8) * 64 + cg4) = wv1;
    __syncthreads();
    int buf = 0;
    for (int kt = 0; kt < K; kt += 16) {
        const bool more = (kt + 16 < K);
        if (more) {
            av  = *(const float4*)(A + (size_t)ar * lda + kt + 16 + ak);
            wv0 = *(const float4*)(W + (size_t)(kt + 16 + wk) * ldw + wcol);
            wv1 = *(const float4*)(W + (size_t)(kt + 24 + wk) * ldw + wcol);
        }
        const float* as = a_sm + buf * (16 * 32);
        const float* ws = w_sm + buf * (16 * 64);
        float4 ac = *(const float4*)(as + rg4);
        float4 wc = *(const float4*)(ws + cg4);
#pragma unroll
        for (int k = 0; k < 16; ++k) {
            float4 an = ac, wn = wc;
            if (k + 1 < 16) {
                an = *(const float4*)(as + (k + 1) * 32 + rg4);
                wn = *(const float4*)(ws + (k + 1) * 64 + cg4);
            }
            FMA16(ac, wc)
            ac = an; wc = wn;
        }
        if (more) {
            buf ^= 1;
            float* asn = a_sm + buf * (16 * 32);
            float* wsn = w_sm + buf * (16 * 64);
            asn[(ak + 0) * 32 + ar] = av.x;
            asn[(ak + 1) * 32 + ar] = av.y;
            asn[(ak + 2) * 32 + ar] = av.z;
            asn[(ak + 3) * 32 + ar] = av.w;
            *(float4*)(wsn + wk * 64 + cg4)       = wv0;
            *(float4*)(wsn + (wk + 8) * 64 + cg4) = wv1;
            __syncthreads();
        }
    }
}

__device__ __forceinline__ void gemm_core(
    const float* A1, int lda1, int K1, const float* W1,
    const float* A2, int lda2, int K2, const float* W2,
    int ldw, const float* bias, float* C, int ldc,
    float* a_sm, float* w_sm)
{
    int tid = threadIdx.x;
    int n0 = blockIdx.x * 64, b0 = blockIdx.y * 32;
    int cg4 = (tid & 15) * 4, rg4 = (tid >> 4) * 4;
    int wcol = n0 + cg4;
    float4 bw = *(const float4*)(bias + wcol);
    float acc[4][4];
#pragma unroll
    for (int i = 0; i < 4; ++i) {
        acc[i][0] = bw.x; acc[i][1] = bw.y; acc[i][2] = bw.z; acc[i][3] = bw.w;
    }
    tile_acc128(acc, A1 + (size_t)b0 * lda1, lda1, K1, W1, ldw, wcol, a_sm, w_sm, tid, rg4, cg4);
    if (K2 > 0)
        tile_acc128(acc, A2 + (size_t)b0 * lda2, lda2, K2, W2, ldw, wcol, a_sm, w_sm, tid, rg4, cg4);
#pragma unroll
    for (int i = 0; i < 4; ++i)
        *(float4*)(C + (size_t)(b0 + rg4 + i) * ldc + wcol) =
            make_float4(acc[i][0], acc[i][1], acc[i][2], acc[i][3]);
}

__global__ void __launch_bounds__(128) query_kernel(const float* __restrict__ Wq,
                                                    const float* __restrict__ bq, int s)
{
    __shared__ float a_sm[2 * 16 * 32], w_sm[2 * 16 * 64];
    const float* h1 = g_dh + ((s + 1) & 1) * 2 * BH + BH;
    gemm_core(h1, H, H, Wq, nullptr, 0, 0, nullptr, E2, bq, g_q, E2, a_sm, w_sm);
}

__global__ void __launch_bounds__(128) comb_kernel(const float* __restrict__ Wc,
                                                   const float* __restrict__ bc, int s)
{
    __shared__ float a_sm[2 * 16 * 32], w_sm[2 * 16 * 64];
    const float* h1 = g_dh + ((s + 1) & 1) * 2 * BH + BH;
    gemm_core(h1, H, H, Wc, g_cx, E2, E2, Wc + (size_t)H * H, H, bc, g_cb, H, a_sm, w_sm);
}

__global__ void __launch_bounds__(128) logits_kernel(const float* __restrict__ Wf,
                                                     const float* __restrict__ bf,
                                                     float* __restrict__ out, int s)
{
    __shared__ float a_sm[2 * 16 * 32], w_sm[2 * 16 * 64];
    gemm_core(g_cb, H, H, Wf, nullptr, 0, 0, nullptr, V, bf,
              out + (size_t)s * V, LW * V, a_sm, w_sm);
}

__global__ void __launch_bounds__(256) attn_kernel(float* __restrict__ out, int step)
{
    __shared__ float qs[E2];
    __shared__ float sc[T];
    __shared__ float red[8];
    int b = blockIdx.x, tid = threadIdx.x;
    const float* eb = g_enc + (size_t)b * T * E2;
    for (int j = tid; j < E2; j += 256) qs[j] = g_q[b * E2 + j];
    __syncthreads();
    int warp = tid >> 5, lane = tid & 31;
    for (int t = warp; t < T; t += 8) {
        const float* er = eb + (size_t)t * E2;
        float acc = 0.f;
#pragma unroll 8
        for (int j = lane; j < E2; j += 32) acc += er[j] * qs[j];
#pragma unroll
        for (int o = 16; o; o >>= 1) acc += __shfl_xor_sync(0xffffffffu, acc, o);
        if (lane == 0) sc[t] = acc;
    }
    __syncthreads();
    float v = sc[tid];
    float m = v;
#pragma unroll
    for (int o = 16; o; o >>= 1) m = fmaxf(m, __shfl_xor_sync(0xffffffffu, m, o));
    if (lane == 0) red[warp] = m;
    __syncthreads();
    float bm = red[0];
#pragma unroll
    for (int w = 1; w < 8; ++w) bm = fmaxf(bm, red[w]);
    float e = expf(v - bm);
    float ssum = e;
#pragma unroll
    for (int o = 16; o; o >>= 1) ssum += __shfl_xor_sync(0xffffffffu, ssum, o);
    __syncthreads();
    if (lane == 0) red[warp] = ssum;
    __syncthreads();
    float tot = 0.f;
#pragma unroll
    for (int w = 0; w < 8; ++w) tot += red[w];
    float p = e / tot;
    sc[tid] = p;
    out[OUT_ATT + (size_t)b * T * LW + (size_t)tid * LW + step] = p;
    __syncthreads();
    float a0 = 0.f, a1 = 0.f, a2 = 0.f, a3 = 0.f;
    for (int t = 0; t < T; ++t) {
        float pt = sc[t];
        const float* er = eb + (size_t)t * E2;
        a0 = fmaf(pt, er[tid], a0);
        a1 = fmaf(pt, er[tid + 256], a1);
        a2 = fmaf(pt, er[tid + 512], a2);
        a3 = fmaf(pt, er[tid + 768], a3);
    }
    g_cx[b * E2 + tid]       = a0;
    g_cx[b * E2 + tid + 256] = a1;
    g_cx[b * E2 + tid + 512] = a2;
    g_cx[b * E2 + tid + 768] = a3;
}

__global__ void argmax_kernel(const float* __restrict__ out, int step)
{
    int b = blockIdx.x, tid = threadIdx.x;
    float v = out[(size_t)b * LW * V + (size_t)step * V + tid];
    int idx = tid;
#pragma unroll
    for (int o = 16; o; o >>= 1) {
        float ov = __shfl_xor_sync(0xffffffffu, v, o);
        int oi = __shfl_xor_sync(0xffffffffu, idx, o);
        if (ov > v || (ov == v && oi < idx)) { v = ov; idx = oi; }
    }
    __shared__ float sv[4];
    __shared__ int si[4];
    if ((tid & 31) == 0) { sv[tid >> 5] = v; si[tid >> 5] = idx; }
    __syncthreads();
    if (tid == 0) {
#pragma unroll
        for (int w = 1; w < 4; ++w)
            if (sv[w] > v || (sv[w] == v && si[w] < idx)) { v = sv[w]; idx = si[w]; }
        g_tok[b] = idx;
    }
}

__global__ void gather_emb(const float* __restrict__ emb)
{
    g_din[blockIdx.x * H + threadIdx.x] = emb[(size_t)g_tok[blockIdx.x] * H + threadIdx.x];
}

__global__ void init_tok() { g_tok[threadIdx.x] = 1; }   // SOS = 1

__global__ void zero_enc()
{
    int i = blockIdx.x * blockDim.x + threadIdx.x;
    if (i < 4 * BH) g_eh[i] = 0.f;
    if (i < 2 * BH) g_ec[i] = 0.f;
}

__global__ void sum_states(int l)
{
    int i = blockIdx.x * blockDim.x + threadIdx.x;
    if (i < BH) {
        g_dh[l * BH + i] = g_eh[i] + g_eh[BH + i];
        g_dc[l * BH + i] = g_ec[i] + g_ec[BH + i];
    }
}

__global__ void final_copy(float* __restrict__ out)
{
    int i = blockIdx.x * blockDim.x + threadIdx.x;
    if (i < NL * BH) {
        out[OUT_HF + i] = g_dh[i];
        out[OUT_CF + i] = g_dc[i];
    }
}

extern "C" void kernel_launch(void* const* d_in, const int* in_sizes, int n_in,
                              void* d_out, int out_size)
{
    const float* x     = (const float*)d_in[0];
    const float* e0Wih = (const float*)d_in[1];
    const float* e0Whh = (const float*)d_in[2];
    const float* e0b   = (const float*)d_in[3];
    const float* e1Wih = (const float*)d_in[4];
    const float* e1Whh = (const float*)d_in[5];
    const float* e1b   = (const float*)d_in[6];
    const float* dWih  = (const float*)d_in[7];
    const float* dWhh  = (const float*)d_in[8];
    const float* db    = (const float*)d_in[9];
    const float* emb   = (const float*)d_in[10];
    const float* Wq    = (const float*)d_in[11];
    const float* bq    = (const float*)d_in[12];
    const float* Wc    = (const float*)d_in[13];
    const float* bc    = (const float*)d_in[14];
    const float* Wf    = (const float*)d_in[15];
    const float* bf    = (const float*)d_in[16];
    float* out = (float*)d_out;

    dim3 gL(16, 8, 2), gD(16, 8, 1);

    zero_enc<<<(4 * BH + 255) / 256, 256>>>();
    for (int s = 0; s < T; ++s)
        enc0_step<<<gL, 128>>>(x, e0Wih, e0Whh, e0b, s);
    sum_states<<<256, 256>>>(0);

    // hoisted enc1 input projection: one big parallel GEMM over all timesteps
    pre_gemm<<<dim3(64, 512), 256>>>(e1Wih, e1b);

    zero_enc<<<(4 * BH + 255) / 256, 256>>>();
    for (int s = 0; s < T; ++s)
        enc1_step<<<gL, 128>>>(e1Whh, s);
    sum_states<<<256, 256>>>(1);

    init_tok<<<1, B>>>();
    for (int s = 0; s < LW; ++s) {
        gather_emb<<<B, H>>>(emb);
        dec_step<<<gD, 128>>>(dWih, dWhh, db, 0, s);
        dec_step<<<gD, 128>>>(dWih, dWhh, db, 1, s);
        query_kernel<<<dim3(16, 4), 128>>>(Wq, bq, s);
        attn_kernel<<<B, 256>>>(out, s);
        comb_kernel<<<dim3(8, 4), 128>>>(Wc, bc, s);
        logits_kernel<<<dim3(2, 4), 128>>>(Wf, bf, out, s);
        argmax_kernel<<<B, 128>>>(out, s);
    }
    final_copy<<<512, 256>>>(out);
}

// round 16
// speedup vs baseline: 1.3582x; 1.2126x over previous
#include <cuda_runtime.h>
#include <cuda_bf16.h>
#include <cstdint>
#include <math.h>

static constexpr int H  = 512;
static constexpr int G4 = 2048;
static constexpr int B  = 128;
static constexpr int T  = 256;
static constexpr int V  = 128;
static constexpr int LW = 32;
static constexpr int NL = 2;
static constexpr int BH = B * H;
static constexpr int E2 = 2 * H;
static constexpr int KC = 32;       // k-chunk for fp32 LSTM tiles
static constexpr int AS = 20;       // a_sm row stride (pad)

static constexpr long OUT_HF  = (long)B * LW * V;
static constexpr long OUT_CF  = OUT_HF + (long)NL * BH;
static constexpr long OUT_ATT = OUT_CF + (long)NL * BH;

static constexpr int MROWS = T * B;       // 32768
static constexpr int NCOLS = 2 * G4;      // 4096
static constexpr int KDIM  = E2;          // 1024
static constexpr int SMS   = 40;          // smem bf16 row stride for mma tiles

// ---- scratch (device globals; no runtime allocation) ----
__device__ float g_l0[(size_t)T * B * E2];    // layer0 out [t][b][2H]
__device__ float g_pre[(size_t)MROWS * NCOLS];// enc1 input-proj gates
__device__ float g_enc[(size_t)B * T * E2];   // encoder out [b][t][2H]
__device__ float g_eh[2 * 2 * BH];
__device__ float g_ec[2 * BH];
__device__ float g_dh[2 * 2 * BH];
__device__ float g_dc[2 * BH];
__device__ float g_din[BH];
__device__ float g_q[B * E2];
__device__ float g_cx[B * E2];
__device__ float g_cb[BH];
__device__ int   g_tok[B];
// bf16 split operands for the tensor pre-GEMM
__device__ __align__(256) __nv_bfloat16 g_Ah[(size_t)MROWS * KDIM];
__device__ __align__(256) __nv_bfloat16 g_Al[(size_t)MROWS * KDIM];
__device__ __align__(256) __nv_bfloat16 g_Bh[(size_t)NCOLS * KDIM];  // W^T [n][k]
__device__ __align__(256) __nv_bfloat16 g_Bl[(size_t)NCOLS * KDIM];

__device__ __forceinline__ float sigf(float x) { return 1.0f / (1.0f + expf(-x)); }

__device__ __forceinline__ uint32_t smem_to_u32(const void* p) {
    uint32_t a;
    asm("{ .reg .u64 t; cvta.to.shared.u64 t, %1; cvt.u32.u64 %0, t; }" : "=r"(a) : "l"(p));
    return a;
}
#define CP_ASYNC_16(dst, src) \
    asm volatile("cp.async.ca.shared.global [%0], [%1], 16;" :: "r"(dst), "l"(src))
#define CP_COMMIT() asm volatile("cp.async.commit_group;" ::: "memory")
#define CP_WAIT0()  asm volatile("cp.async.wait_group 0;" ::: "memory")
#define CP_WAIT1()  asm volatile("cp.async.wait_group 1;" ::: "memory")

__device__ __forceinline__ void mma_bf16(float* d, const uint32_t* a, const uint32_t* b)
{
    asm volatile("mma.sync.aligned.m16n8k16.row.col.f32.bf16.bf16.f32 "
        "{%0,%1,%2,%3}, {%4,%5,%6,%7}, {%8,%9}, {%0,%1,%2,%3};"
        : "+f"(d[0]), "+f"(d[1]), "+f"(d[2]), "+f"(d[3])
        : "r"(a[0]), "r"(a[1]), "r"(a[2]), "r"(a[3]), "r"(b[0]), "r"(b[1]));
}

// ===== pre_mma: g_pre[m][n] = bias[n] + sum_k A[m][k]*W[k][n], split-bf16 HMMA =====
// block tile 128x128, 256 threads (8 warps: wm=wid>>2 in {0,1} x wn=wid&3 in 0..3),
// warp tile 64x32 (4 m-tiles x 4 n-tiles of m16n8k16). cp.async double-buffered k=32.
__global__ void __launch_bounds__(256) pre_mma(const float* __restrict__ bias)
{
    __shared__ __nv_bfloat16 SAh[2][128 * SMS];
    __shared__ __nv_bfloat16 SAl[2][128 * SMS];
    __shared__ __nv_bfloat16 SBh[2][128 * SMS];
    __shared__ __nv_bfloat16 SBl[2][128 * SMS];

    const int tid = threadIdx.x;
    const int wid = tid >> 5, lane = tid & 31;
    const int wm = wid >> 2, wn = wid & 3;
    const int g = lane >> 2, tig = lane & 3;
    const int n0 = blockIdx.x * 128;
    const size_t m0 = (size_t)blockIdx.y * 128;

    const int lrow = tid >> 1;           // 0..127
    const int koff = (tid & 1) * 16;     // 0 or 16
    const uint32_t sAh0 = smem_to_u32(&SAh[0][0]);
    const uint32_t sAl0 = smem_to_u32(&SAl[0][0]);
    const uint32_t sBh0 = smem_to_u32(&SBh[0][0]);
    const uint32_t sBl0 = smem_to_u32(&SBl[0][0]);
    const uint32_t dstoff = (uint32_t)(lrow * SMS + koff) * 2;  // bytes
    const uint32_t bufstep = 128 * SMS * 2;

    auto issue = [&](int kt, int buf) {
        const __nv_bfloat16* a0 = g_Ah + (m0 + lrow) * KDIM + kt + koff;
        const __nv_bfloat16* a1 = g_Al + (m0 + lrow) * KDIM + kt + koff;
        const __nv_bfloat16* b0 = g_Bh + ((size_t)n0 + lrow) * KDIM + kt + koff;
        const __nv_bfloat16* b1 = g_Bl + ((size_t)n0 + lrow) * KDIM + kt + koff;
        uint32_t off = buf * bufstep + dstoff;
        CP_ASYNC_16(sAh0 + off, a0);
        CP_ASYNC_16(sAh0 + off + 16, a0 + 8);
        CP_ASYNC_16(sAl0 + off, a1);
        CP_ASYNC_16(sAl0 + off + 16, a1 + 8);
        CP_ASYNC_16(sBh0 + off, b0);
        CP_ASYNC_16(sBh0 + off + 16, b0 + 8);
        CP_ASYNC_16(sBl0 + off, b1);
        CP_ASYNC_16(sBl0 + off + 16, b1 + 8);
        CP_COMMIT();
    };

    float acc[4][4][4];
#pragma unroll
    for (int i = 0; i < 4; ++i)
#pragma unroll
        for (int j = 0; j < 4; ++j)
#pragma unroll
            for (int q = 0; q < 4; ++q) acc[i][j][q] = 0.f;

    issue(0, 0);
    int buf = 0;
    const int NCHUNK = KDIM / 32;  // 32
    for (int ch = 0; ch < NCHUNK; ++ch) {
        if (ch + 1 < NCHUNK) { issue((ch + 1) * 32, buf ^ 1); CP_WAIT1(); }
        else                 { CP_WAIT0(); }
        __syncthreads();
#pragma unroll
        for (int k0 = 0; k0 < 32; k0 += 16) {
            uint32_t bh[4][2], bl[4][2], af[4][4];
#pragma unroll
            for (int nt = 0; nt < 4; ++nt) {
                const __nv_bfloat16* bp = &SBh[buf][(wn * 32 + nt * 8 + g) * SMS + k0 + tig * 2];
                bh[nt][0] = *(const uint32_t*)bp;
                bh[nt][1] = *(const uint32_t*)(bp + 8);
                const __nv_bfloat16* bq = &SBl[buf][(wn * 32 + nt * 8 + g) * SMS + k0 + tig * 2];
                bl[nt][0] = *(const uint32_t*)bq;
                bl[nt][1] = *(const uint32_t*)(bq + 8);
            }
#pragma unroll
            for (int mt = 0; mt < 4; ++mt) {
                const __nv_bfloat16* ap = &SAh[buf][(wm * 64 + mt * 16 + g) * SMS + k0 + tig * 2];
                af[mt][0] = *(const uint32_t*)ap;
                af[mt][1] = *(const uint32_t*)(ap + 8 * SMS);
                af[mt][2] = *(const uint32_t*)(ap + 8);
                af[mt][3] = *(const uint32_t*)(ap + 8 * SMS + 8);
            }
#pragma unroll
            for (int mt = 0; mt < 4; ++mt)
#pragma unroll
                for (int nt = 0; nt < 4; ++nt) {
                    mma_bf16(acc[mt][nt], af[mt], bh[nt]);
                    mma_bf16(acc[mt][nt], af[mt], bl[nt]);
                }
#pragma unroll
            for (int mt = 0; mt < 4; ++mt) {
                const __nv_bfloat16* ap = &SAl[buf][(wm * 64 + mt * 16 + g) * SMS + k0 + tig * 2];
                af[mt][0] = *(const uint32_t*)ap;
                af[mt][1] = *(const uint32_t*)(ap + 8 * SMS);
                af[mt][2] = *(const uint32_t*)(ap + 8);
                af[mt][3] = *(const uint32_t*)(ap + 8 * SMS + 8);
            }
#pragma unroll
            for (int mt = 0; mt < 4; ++mt)
#pragma unroll
                for (int nt = 0; nt < 4; ++nt)
                    mma_bf16(acc[mt][nt], af[mt], bh[nt]);
        }
        __syncthreads();
        buf ^= 1;
    }

    // epilogue: acc -> g_pre with bias
#pragma unroll
    for (int mt = 0; mt < 4; ++mt) {
        size_t r0 = m0 + wm * 64 + mt * 16 + g;
        size_t r8 = r0 + 8;
#pragma unroll
        for (int nt = 0; nt < 4; ++nt) {
            int col = n0 + wn * 32 + nt * 8 + tig * 2;
            float b0v = bias[col], b1v = bias[col + 1];
            float2 v0 = make_float2(acc[mt][nt][0] + b0v, acc[mt][nt][1] + b1v);
            float2 v1 = make_float2(acc[mt][nt][2] + b0v, acc[mt][nt][3] + b1v);
            *(float2*)(g_pre + r0 * NCOLS + col) = v0;
            *(float2*)(g_pre + r8 * NCOLS + col) = v1;
        }
    }
}

// conversion kernels
__global__ void conv_A()
{
    size_t i = (size_t)blockIdx.x * blockDim.x + threadIdx.x;
    float v = g_l0[i];
    __nv_bfloat16 hi = __float2bfloat16(v);
    g_Ah[i] = hi;
    g_Al[i] = __float2bfloat16(v - __bfloat162float(hi));
}
__global__ void conv_W(const float* __restrict__ Wih)
{
    size_t i = (size_t)blockIdx.x * blockDim.x + threadIdx.x;
    int n = (int)(i >> 10), k = (int)(i & 1023);
    float v = Wih[(size_t)(n >> 11) * KDIM * G4 + (size_t)k * G4 + (n & 2047)];
    __nv_bfloat16 hi = __float2bfloat16(v);
    g_Bh[i] = hi;
    g_Bl[i] = __float2bfloat16(v - __bfloat162float(hi));
}

#define FMA16(ac, wc)                                   \
    acc[0][0] = fmaf(ac.x, wc.x, acc[0][0]);            \
    acc[0][1] = fmaf(ac.x, wc.y, acc[0][1]);            \
    acc[0][2] = fmaf(ac.x, wc.z, acc[0][2]);            \
    acc[0][3] = fmaf(ac.x, wc.w, acc[0][3]);            \
    acc[1][0] = fmaf(ac.y, wc.x, acc[1][0]);            \
    acc[1][1] = fmaf(ac.y, wc.y, acc[1][1]);            \
    acc[1][2] = fmaf(ac.y, wc.z, acc[1][2]);            \
    acc[1][3] = fmaf(ac.y, wc.w, acc[1][3]);            \
    acc[2][0] = fmaf(ac.z, wc.x, acc[2][0]);            \
    acc[2][1] = fmaf(ac.z, wc.y, acc[2][1]);            \
    acc[2][2] = fmaf(ac.z, wc.z, acc[2][2]);            \
    acc[2][3] = fmaf(ac.z, wc.w, acc[2][3]);            \
    acc[3][0] = fmaf(ac.w, wc.x, acc[3][0]);            \
    acc[3][1] = fmaf(ac.w, wc.y, acc[3][1]);            \
    acc[3][2] = fmaf(ac.w, wc.z, acc[3][2]);            \
    acc[3][3] = fmaf(ac.w, wc.w, acc[3][3]);

// ========== fp32 LSTM GEMM: 16 rows x 128 gate-cols, 128 threads ==========
__device__ __forceinline__ void lstm_tile_acc(float acc[4][4],
    const float* __restrict__ A, int lda, int K,
    const float* __restrict__ W, int ldw, int wcol,
    float* a_sm, float* w_sm, int tid, int rg4, int cg4)
{
    const int ar  = tid & 15;
    const int akk = (tid >> 4) * 4;
    const int wk  = tid >> 5;
    float4 av, wv0, wv1, wv2, wv3, wv4, wv5, wv6, wv7;
    av  = *(const float4*)(A + (size_t)ar * lda + akk);
    wv0 = *(const float4*)(W + (size_t)(wk +  0) * ldw + wcol);
    wv1 = *(const float4*)(W + (size_t)(wk +  4) * ldw + wcol);
    wv2 = *(const float4*)(W + (size_t)(wk +  8) * ldw + wcol);
    wv3 = *(const float4*)(W + (size_t)(wk + 12) * ldw + wcol);
    wv4 = *(const float4*)(W + (size_t)(wk + 16) * ldw + wcol);
    wv5 = *(const float4*)(W + (size_t)(wk + 20) * ldw + wcol);
    wv6 = *(const float4*)(W + (size_t)(wk + 24) * ldw + wcol);
    wv7 = *(const float4*)(W + (size_t)(wk + 28) * ldw + wcol);
    __syncthreads();
    a_sm[(akk + 0) * AS + ar] = av.x;
    a_sm[(akk + 1) * AS + ar] = av.y;
    a_sm[(akk + 2) * AS + ar] = av.z;
    a_sm[(akk + 3) * AS + ar] = av.w;
    *(float4*)(w_sm + (wk +  0) * 128 + cg4) = wv0;
    *(float4*)(w_sm + (wk +  4) * 128 + cg4) = wv1;
    *(float4*)(w_sm + (wk +  8) * 128 + cg4) = wv2;
    *(float4*)(w_sm + (wk + 12) * 128 + cg4) = wv3;
    *(float4*)(w_sm + (wk + 16) * 128 + cg4) = wv4;
    *(float4*)(w_sm + (wk + 20) * 128 + cg4) = wv5;
    *(float4*)(w_sm + (wk + 24) * 128 + cg4) = wv6;
    *(float4*)(w_sm + (wk + 28) * 128 + cg4) = wv7;
    __syncthreads();
    int buf = 0;
    for (int kt = 0; kt < K; kt += KC) {
        const bool more = (kt + KC < K);
        if (more) {
            const float* An = A + (size_t)ar * lda + kt + KC;
            const float* Wn = W + (size_t)(kt + KC) * ldw + wcol;
            av  = *(const float4*)(An + akk);
            wv0 = *(const float4*)(Wn + (size_t)(wk +  0) * ldw);
            wv1 = *(const float4*)(Wn + (size_t)(wk +  4) * ldw);
            wv2 = *(const float4*)(Wn + (size_t)(wk +  8) * ldw);
            wv3 = *(const float4*)(Wn + (size_t)(wk + 12) * ldw);
            wv4 = *(const float4*)(Wn + (size_t)(wk + 16) * ldw);
            wv5 = *(const float4*)(Wn + (size_t)(wk + 20) * ldw);
            wv6 = *(const float4*)(Wn + (size_t)(wk + 24) * ldw);
            wv7 = *(const float4*)(Wn + (size_t)(wk + 28) * ldw);
        }
        const float* as = a_sm + buf * (KC * AS);
        const float* ws = w_sm + buf * (KC * 128);
        float4 ac = *(const float4*)(as + rg4);
        float4 wc = *(const float4*)(ws + cg4);
#pragma unroll
        for (int k = 0; k < KC; ++k) {
            float4 an = ac, wn = wc;
            if (k + 1 < KC) {
                an = *(const float4*)(as + (k + 1) * AS + rg4);
                wn = *(const float4*)(ws + (k + 1) * 128 + cg4);
            }
            FMA16(ac, wc)
            ac = an; wc = wn;
        }
        if (more) {
            buf ^= 1;
            float* asn = a_sm + buf * (KC * AS);
            float* wsn = w_sm + buf * (KC * 128);
            asn[(akk + 0) * AS + ar] = av.x;
            asn[(akk + 1) * AS + ar] = av.y;
            asn[(akk + 2) * AS + ar] = av.z;
            asn[(akk + 3) * AS + ar] = av.w;
            *(float4*)(wsn + (wk +  0) * 128 + cg4) = wv0;
            *(float4*)(wsn + (wk +  4) * 128 + cg4) = wv1;
            *(float4*)(wsn + (wk +  8) * 128 + cg4) = wv2;
            *(float4*)(wsn + (wk + 12) * 128 + cg4) = wv3;
            *(float4*)(wsn + (wk + 16) * 128 + cg4) = wv4;
            *(float4*)(wsn + (wk + 20) * 128 + cg4) = wv5;
            *(float4*)(wsn + (wk + 24) * 128 + cg4) = wv6;
            *(float4*)(wsn + (wk + 28) * 128 + cg4) = wv7;
            __syncthreads();
        }
    }
}

__device__ __forceinline__ void cell_update16(const float* gs, int tid, int b0, int u0,
    float* __restrict__ cd, float* __restrict__ hd,
    float* __restrict__ seqbase, size_t sbstride)
{
#pragma unroll
    for (int q = 0; q < 4; ++q) {
        int flat = tid * 4 + q;
        int r = flat >> 5, u = flat & 31;
        int b = b0 + r, uu = u0 + u;
        float iv = gs[r * 128 + u];
        float fv = gs[r * 128 + 32 + u];
        float gv = gs[r * 128 + 64 + u];
        float ov = gs[r * 128 + 96 + u];
        float cn = sigf(fv) * cd[b * H + uu] + sigf(iv) * tanhf(gv);
        float hn = sigf(ov) * tanhf(cn);
        cd[b * H + uu] = cn;
        hd[b * H + uu] = hn;
        if (seqbase) seqbase[(size_t)b * sbstride + uu] = hn;
    }
}

__global__ void __launch_bounds__(128) enc0_step(
    const float* __restrict__ x, const float* __restrict__ Wih,
    const float* __restrict__ Whh, const float* __restrict__ bias, int s)
{
    __shared__ float a_sm[2 * KC * AS];
    __shared__ float w_sm[2 * KC * 128];
    int tid = threadIdx.x, dir = blockIdx.z;
    int t = dir ? (T - 1 - s) : s;
    int u0 = blockIdx.x * 32, b0 = blockIdx.y * 16;
    int cg4 = (tid & 31) * 4;
    int rg4 = (tid >> 5) * 4;
    int wcol = (cg4 >> 5) * H + u0 + (cg4 & 31);

    const float* Wd  = Wih + dir * 2 * G4;
    const float* Whd = Whh + (size_t)dir * H * G4;
    const float* bd  = bias + dir * G4;
    float* hin  = g_eh + (s & 1) * 2 * BH + dir * BH;
    float* hout = g_eh + ((s + 1) & 1) * 2 * BH + dir * BH;
    float* cd   = g_ec + dir * BH;

    float4 bw  = *(const float4*)(bd + wcol);
    float4 wi0 = *(const float4*)(Wd + wcol);
    float4 wi1 = *(const float4*)(Wd + G4 + wcol);
    float acc[4][4];
#pragma unroll
    for (int i = 0; i < 4; ++i) {
        int b = b0 + rg4 + i;
        float x0 = x[(size_t)b * T * 2 + t * 2 + 0];
        float x1 = x[(size_t)b * T * 2 + t * 2 + 1];
        acc[i][0] = bw.x + x0 * wi0.x + x1 * wi1.x;
        acc[i][1] = bw.y + x0 * wi0.y + x1 * wi1.y;
        acc[i][2] = bw.z + x0 * wi0.z + x1 * wi1.z;
        acc[i][3] = bw.w + x0 * wi0.w + x1 * wi1.w;
    }
    lstm_tile_acc(acc, hin + (size_t)b0 * H, H, H, Whd, G4, wcol, a_sm, w_sm, tid, rg4, cg4);
    __syncthreads();
#pragma unroll
    for (int i = 0; i < 4; ++i)
#pragma unroll
        for (int j = 0; j < 4; ++j)
            w_sm[(rg4 + i) * 128 + cg4 + j] = acc[i][j];
    __syncthreads();
    cell_update16(w_sm, tid, b0, u0, cd, hout,
                  g_l0 + (size_t)t * B * E2 + dir * H, E2);
}

__global__ void __launch_bounds__(128) enc1_step(
    const float* __restrict__ Whh, int s)
{
    __shared__ float a_sm[2 * KC * AS];
    __shared__ float w_sm[2 * KC * 128];
    int tid = threadIdx.x, dir = blockIdx.z;
    int t = dir ? (T - 1 - s) : s;
    int u0 = blockIdx.x * 32, b0 = blockIdx.y * 16;
    int cg4 = (tid & 31) * 4;
    int rg4 = (tid >> 5) * 4;
    int wcol = (cg4 >> 5) * H + u0 + (cg4 & 31);

    const float* Whd = Whh + (size_t)dir * H * G4;
    float* hin  = g_eh + (s & 1) * 2 * BH + dir * BH;
    float* hout = g_eh + ((s + 1) & 1) * 2 * BH + dir * BH;
    float* cd   = g_ec + dir * BH;

    const float* pre = g_pre + ((size_t)t * B + b0) * NCOLS + dir * G4;
    float acc[4][4];
#pragma unroll
    for (int i = 0; i < 4; ++i) {
        float4 pv = *(const float4*)(pre + (size_t)(rg4 + i) * NCOLS + wcol);
        acc[i][0] = pv.x; acc[i][1] = pv.y; acc[i][2] = pv.z; acc[i][3] = pv.w;
    }
    lstm_tile_acc(acc, hin + (size_t)b0 * H, H, H, Whd, G4, wcol, a_sm, w_sm, tid, rg4, cg4);
    __syncthreads();
#pragma unroll
    for (int i = 0; i < 4; ++i)
#pragma unroll
        for (int j = 0; j < 4; ++j)
            w_sm[(rg4 + i) * 128 + cg4 + j] = acc[i][j];
    __syncthreads();
    cell_update16(w_sm, tid, b0, u0, cd, hout,
                  g_enc + (size_t)t * E2 + dir * H, (size_t)T * E2);
}

__global__ void __launch_bounds__(128) dec_step(
    const float* __restrict__ Wih, const float* __restrict__ Whh,
    const float* __restrict__ bias, int layer, int s)
{
    __shared__ float a_sm[2 * KC * AS];
    __shared__ float w_sm[2 * KC * 128];
    int tid = threadIdx.x;
    int u0 = blockIdx.x * 32, b0 = blockIdx.y * 16;
    int cg4 = (tid & 31) * 4;
    int rg4 = (tid >> 5) * 4;
    int wcol = (cg4 >> 5) * H + u0 + (cg4 & 31);

    const float* Wd  = Wih + (size_t)layer * H * G4;
    const float* Whd = Whh + (size_t)layer * H * G4;
    const float* bd  = bias + layer * G4;
    const float* A1  = (layer == 0) ? g_din : (g_dh + ((s + 1) & 1) * 2 * BH);
    float* hin  = g_dh + (s & 1) * 2 * BH + layer * BH;
    float* hout = g_dh + ((s + 1) & 1) * 2 * BH + layer * BH;
    float* cd   = g_dc + layer * BH;

    float4 bw = *(const float4*)(bd + wcol);
    float acc[4][4];
#pragma unroll
    for (int i = 0; i < 4; ++i) {
        acc[i][0] = bw.x; acc[i][1] = bw.y; acc[i][2] = bw.z; acc[i][3] = bw.w;
    }
    lstm_tile_acc(acc, A1 + (size_t)b0 * H, H, H, Wd, G4, wcol, a_sm, w_sm, tid, rg4, cg4);
    lstm_tile_acc(acc, hin + (size_t)b0 * H, H, H, Whd, G4, wcol, a_sm, w_sm, tid, rg4, cg4);
    __syncthreads();
#pragma unroll
    for (int i = 0; i < 4; ++i)
#pragma unroll
        for (int j = 0; j < 4; ++j)
            w_sm[(rg4 + i) * 128 + cg4 + j] = acc[i][j];
    __syncthreads();
    cell_update16(w_sm, tid, b0, u0, cd, hout, nullptr, 0);
}

// ================= small GEMMs (query/comb/logits) =================
__device__ __forceinline__ void tile_acc128(float acc[4][4],
    const float* __restrict__ A, int lda, int K,
    const float* __restrict__ W, int ldw, int wcol,
    float* a_sm, float* w_sm, int tid, int rg4, int cg4)
{
    const int ar = tid >> 2;
    const int ak = (tid & 3) << 2;
    const int wk = tid >> 4;
    float4 av  = *(const float4*)(A + (size_t)ar * lda + ak);
    float4 wv0 = *(const float4*)(W + (size_t)wk * ldw + wcol);
    float4 wv1 = *(const float4*)(W + (size_t)(wk + 8) * ldw + wcol);
    __syncthreads();
    a_sm[(ak + 0) * 32 + ar] = av.x;
    a_sm[(ak + 1) * 32 + ar] = av.y;
    a_sm[(ak + 2) * 32 + ar] = av.z;
    a_sm[(ak + 3) * 32 + ar] = av.w;
    *(float4*)(w_sm + wk * 64 + cg4)       = wv0;
    *(float4*)(w_sm + (wk + 8) * 64 + cg4) = wv1;
    __syncthreads();
    int buf = 0;
    for (int kt = 0; kt < K; kt += 16) {
        const bool more = (kt + 16 < K);
        if (more) {
            av  = *(const float4*)(A + (size_t)ar * lda + kt + 16 + ak);
            wv0 = *(const float4*)(W + (size_t)(kt + 16 + wk) * ldw + wcol);
            wv1 = *(const float4*)(W + (size_t)(kt + 24 + wk) * ldw + wcol);
        }
        const float* as = a_sm + buf * (16 * 32);
        const float* ws = w_sm + buf * (16 * 64);
        float4 ac = *(const float4*)(as + rg4);
        float4 wc = *(const float4*)(ws + cg4);
#pragma unroll
        for (int k = 0; k < 16; ++k) {
            float4 an = ac, wn = wc;
            if (k + 1 < 16) {
                an = *(const float4*)(as + (k + 1) * 32 + rg4);
                wn = *(const float4*)(ws + (k + 1) * 64 + cg4);
            }
            FMA16(ac, wc)
            ac = an; wc = wn;
        }
        if (more) {
            buf ^= 1;
            float* asn = a_sm + buf * (16 * 32);
            float* wsn = w_sm + buf * (16 * 64);
            asn[(ak + 0) * 32 + ar] = av.x;
            asn[(ak + 1) * 32 + ar] = av.y;
            asn[(ak + 2) * 32 + ar] = av.z;
            asn[(ak + 3) * 32 + ar] = av.w;
            *(float4*)(wsn + wk * 64 + cg4)       = wv0;
            *(float4*)(wsn + (wk + 8) * 64 + cg4) = wv1;
            __syncthreads();
        }
    }
}

__device__ __forceinline__ void gemm_core(
    const float* A1, int lda1, int K1, const float* W1,
    const float* A2, int lda2, int K2, const float* W2,
    int ldw, const float* bias, float* C, int ldc,
    float* a_sm, float* w_sm)
{
    int tid = threadIdx.x;
    int n0 = blockIdx.x * 64, b0 = blockIdx.y * 32;
    int cg4 = (tid & 15) * 4, rg4 = (tid >> 4) * 4;
    int wcol = n0 + cg4;
    float4 bw = *(const float4*)(bias + wcol);
    float acc[4][4];
#pragma unroll
    for (int i = 0; i < 4; ++i) {
        acc[i][0] = bw.x; acc[i][1] = bw.y; acc[i][2] = bw.z; acc[i][3] = bw.w;
    }
    tile_acc128(acc, A1 + (size_t)b0 * lda1, lda1, K1, W1, ldw, wcol, a_sm, w_sm, tid, rg4, cg4);
    if (K2 > 0)
        tile_acc128(acc, A2 + (size_t)b0 * lda2, lda2, K2, W2, ldw, wcol, a_sm, w_sm, tid, rg4, cg4);
#pragma unroll
    for (int i = 0; i < 4; ++i)
        *(float4*)(C + (size_t)(b0 + rg4 + i) * ldc + wcol) =
            make_float4(acc[i][0], acc[i][1], acc[i][2], acc[i][3]);
}

__global__ void __launch_bounds__(128) query_kernel(const float* __restrict__ Wq,
                                                    const float* __restrict__ bq, int s)
{
    __shared__ float a_sm[2 * 16 * 32], w_sm[2 * 16 * 64];
    const float* h1 = g_dh + ((s + 1) & 1) * 2 * BH + BH;
    gemm_core(h1, H, H, Wq, nullptr, 0, 0, nullptr, E2, bq, g_q, E2, a_sm, w_sm);
}

__global__ void __launch_bounds__(128) comb_kernel(const float* __restrict__ Wc,
                                                   const float* __restrict__ bc, int s)
{
    __shared__ float a_sm[2 * 16 * 32], w_sm[2 * 16 * 64];
    const float* h1 = g_dh + ((s + 1) & 1) * 2 * BH + BH;
    gemm_core(h1, H, H, Wc, g_cx, E2, E2, Wc + (size_t)H * H, H, bc, g_cb, H, a_sm, w_sm);
}

__global__ void __launch_bounds__(128) logits_kernel(const float* __restrict__ Wf,
                                                     const float* __restrict__ bf,
                                                     float* __restrict__ out, int s)
{
    __shared__ float a_sm[2 * 16 * 32], w_sm[2 * 16 * 64];
    gemm_core(g_cb, H, H, Wf, nullptr, 0, 0, nullptr, V, bf,
              out + (size_t)s * V, LW * V, a_sm, w_sm);
}

__global__ void __launch_bounds__(256) attn_kernel(float* __restrict__ out, int step)
{
    __shared__ float qs[E2];
    __shared__ float sc[T];
    __shared__ float red[8];
    int b = blockIdx.x, tid = threadIdx.x;
    const float* eb = g_enc + (size_t)b * T * E2;
    for (int j = tid; j < E2; j += 256) qs[j] = g_q[b * E2 + j];
    __syncthreads();
    int warp = tid >> 5, lane = tid & 31;
    for (int t = warp; t < T; t += 8) {
        const float* er = eb + (size_t)t * E2;
        float acc = 0.f;
#pragma unroll 8
        for (int j = lane; j < E2; j += 32) acc += er[j] * qs[j];
#pragma unroll
        for (int o = 16; o; o >>= 1) acc += __shfl_xor_sync(0xffffffffu, acc, o);
        if (lane == 0) sc[t] = acc;
    }
    __syncthreads();
    float v = sc[tid];
    float m = v;
#pragma unroll
    for (int o = 16; o; o >>= 1) m = fmaxf(m, __shfl_xor_sync(0xffffffffu, m, o));
    if (lane == 0) red[warp] = m;
    __syncthreads();
    float bm = red[0];
#pragma unroll
    for (int w = 1; w < 8; ++w) bm = fmaxf(bm, red[w]);
    float e = expf(v - bm);
    float ssum = e;
#pragma unroll
    for (int o = 16; o; o >>= 1) ssum += __shfl_xor_sync(0xffffffffu, ssum, o);
    __syncthreads();
    if (lane == 0) red[warp] = ssum;
    __syncthreads();
    float tot = 0.f;
#pragma unroll
    for (int w = 0; w < 8; ++w) tot += red[w];
    float p = e / tot;
    sc[tid] = p;
    out[OUT_ATT + (size_t)b * T * LW + (size_t)tid * LW + step] = p;
    __syncthreads();
    float a0 = 0.f, a1 = 0.f, a2 = 0.f, a3 = 0.f;
    for (int t = 0; t < T; ++t) {
        float pt = sc[t];
        const float* er = eb + (size_t)t * E2;
        a0 = fmaf(pt, er[tid], a0);
        a1 = fmaf(pt, er[tid + 256], a1);
        a2 = fmaf(pt, er[tid + 512], a2);
        a3 = fmaf(pt, er[tid + 768], a3);
    }
    g_cx[b * E2 + tid]       = a0;
    g_cx[b * E2 + tid + 256] = a1;
    g_cx[b * E2 + tid + 512] = a2;
    g_cx[b * E2 + tid + 768] = a3;
}

__global__ void argmax_kernel(const float* __restrict__ out, int step)
{
    int b = blockIdx.x, tid = threadIdx.x;
    float v = out[(size_t)b * LW * V + (size_t)step * V + tid];
    int idx = tid;
#pragma unroll
    for (int o = 16; o; o >>= 1) {
        float ov = __shfl_xor_sync(0xffffffffu, v, o);
        int oi = __shfl_xor_sync(0xffffffffu, idx, o);
        if (ov > v || (ov == v && oi < idx)) { v = ov; idx = oi; }
    }
    __shared__ float sv[4];
    __shared__ int si[4];
    if ((tid & 31) == 0) { sv[tid >> 5] = v; si[tid >> 5] = idx; }
    __syncthreads();
    if (tid == 0) {
#pragma unroll
        for (int w = 1; w < 4; ++w)
            if (sv[w] > v || (sv[w] == v && si[w] < idx)) { v = sv[w]; idx = si[w]; }
        g_tok[b] = idx;
    }
}

__global__ void gather_emb(const float* __restrict__ emb)
{
    g_din[blockIdx.x * H + threadIdx.x] = emb[(size_t)g_tok[blockIdx.x] * H + threadIdx.x];
}

__global__ void init_tok() { g_tok[threadIdx.x] = 1; }   // SOS = 1

__global__ void zero_enc()
{
    int i = blockIdx.x * blockDim.x + threadIdx.x;
    if (i < 4 * BH) g_eh[i] = 0.f;
    if (i < 2 * BH) g_ec[i] = 0.f;
}

__global__ void sum_states(int l)
{
    int i = blockIdx.x * blockDim.x + threadIdx.x;
    if (i < BH) {
        g_dh[l * BH + i] = g_eh[i] + g_eh[BH + i];
        g_dc[l * BH + i] = g_ec[i] + g_ec[BH + i];
    }
}

__global__ void final_copy(float* __restrict__ out)
{
    int i = blockIdx.x * blockDim.x + threadIdx.x;
    if (i < NL * BH) {
        out[OUT_HF + i] = g_dh[i];
        out[OUT_CF + i] = g_dc[i];
    }
}

extern "C" void kernel_launch(void* const* d_in, const int* in_sizes, int n_in,
                              void* d_out, int out_size)
{
    const float* x     = (const float*)d_in[0];
    const float* e0Wih = (const float*)d_in[1];
    const float* e0Whh = (const float*)d_in[2];
    const float* e0b   = (const float*)d_in[3];
    const float* e1Wih = (const float*)d_in[4];
    const float* e1Whh = (const float*)d_in[5];
    const float* e1b   = (const float*)d_in[6];
    const float* dWih  = (const float*)d_in[7];
    const float* dWhh  = (const float*)d_in[8];
    const float* db    = (const float*)d_in[9];
    const float* emb   = (const float*)d_in[10];
    const float* Wq    = (const float*)d_in[11];
    const float* bq    = (const float*)d_in[12];
    const float* Wc    = (const float*)d_in[13];
    const float* bc    = (const float*)d_in[14];
    const float* Wf    = (const float*)d_in[15];
    const float* bf    = (const float*)d_in[16];
    float* out = (float*)d_out;

    dim3 gL(16, 8, 2), gD(16, 8, 1);

    zero_enc<<<(4 * BH + 255) / 256, 256>>>();
    for (int s = 0; s < T; ++s)
        enc0_step<<<gL, 128>>>(x, e0Wih, e0Whh, e0b, s);
    sum_states<<<256, 256>>>(0);

    // hoisted enc1 input projection on HMMA tensor cores (split-bf16, fp32 accum)
    conv_A<<<(int)(((size_t)MROWS * KDIM) / 256), 256>>>();
    conv_W<<<(int)(((size_t)NCOLS * KDIM) / 256), 256>>>(e1Wih);
    pre_mma<<<dim3(32, 256), 256>>>(e1b);

    zero_enc<<<(4 * BH + 255) / 256, 256>>>();
    for (int s = 0; s < T; ++s)
        enc1_step<<<gL, 128>>>(e1Whh, s);
    sum_states<<<256, 256>>>(1);

    init_tok<<<1, B>>>();
    for (int s = 0; s < LW; ++s) {
        gather_emb<<<B, H>>>(emb);
        dec_step<<<gD, 128>>>(dWih, dWhh, db, 0, s);
        dec_step<<<gD, 128>>>(dWih, dWhh, db, 1, s);
        query_kernel<<<dim3(16, 4), 128>>>(Wq, bq, s);
        attn_kernel<<<B, 256>>>(out, s);
        comb_kernel<<<dim3(8, 4), 128>>>(Wc, bc, s);
        logits_kernel<<<dim3(2, 4), 128>>>(Wf, bf, out, s);
        argmax_kernel<<<B, 128>>>(out, s);
    }
    final_copy<<<512, 256>>>(out);
}